// round 15
// baseline (speedup 1.0000x reference)
#include <cuda_runtime.h>
#include <cuda_fp16.h>
#include <mma.h>
#include <math.h>

using namespace nvcuda;

#define LL 12
#define BB 4
#define CC 768
#define DD 128
#define HWN 256
#define MAXN 30016
#define NBINS 289          // 17 x 17 possible (x0,y0) patches
#define MAXCHUNK 1024
#define CHSZ 64

// ---------------- scratch (static device arrays; no cudaMalloc) ----------------
__device__ __half d_cw_h[LL * DD * CC];          // fp16 copy of conv_w
__device__ __half d_feat_h[LL * BB * HWN * DD];  // [lb][pix][d], fp16, 3.15 MB
__device__ __half d_gb_h[LL * BB * DD];          // [lb][d] fp16
// W1/W2 in fragment-tiled layout: [head][k][wn][16*16], tile ld = 16
__device__ __half d_W1h[3 * 192 * 128];
__device__ __half d_W1l[3 * 192 * 128];
__device__ __half d_W2h[3 * 128 * 128];
__device__ __half d_W2l[3 * 128 * 128];
__device__ float d_pwv[MAXN * 4];
__device__ float d_wl[MAXN * LL];
__device__ float d_sscale[MAXN];
__device__ int   d_bin[MAXN];
__device__ int   d_binCnt[NBINS];
__device__ int   d_binStart[NBINS];
__device__ int   d_binCursor[NBINS];
__device__ int   d_order[MAXN];
__device__ uint2 d_chunks[MAXCHUNK];   // {bin | cnt<<16, start}
__device__ int   d_numChunks;
__device__ float d_regE;
__device__ float d_regS;

// ---------------- prep: W1/W2 hi-lo split into tiled layout + init ------------------
__global__ __launch_bounds__(256) void prep_kernel(
    const float* __restrict__ W1, const float* __restrict__ W2)
{
    int b = blockIdx.x, t = threadIdx.x;
    if (b < 288) {
        int n = 3 * 192 * 128;
        for (int i = b * 256 + t; i < n; i += 288 * 256) {
            int head = i / (192 * 128);
            int rem = i - head * 192 * 128;
            int row = rem >> 7, col = rem & 127;     // row 0..191, col 0..127
            int k = row >> 4, r = row & 15;
            int wn = col >> 4, c = col & 15;
            int dst = ((head * 12 + k) * 8 + wn) * 256 + r * 16 + c;
            float v = W1[i];
            __half h = __float2half_rn(v);
            d_W1h[dst] = h;
            d_W1l[dst] = __float2half_rn(v - __half2float(h));
        }
    } else if (b < 384) {
        int n = 3 * 128 * 128;
        for (int i = (b - 288) * 256 + t; i < n; i += 96 * 256) {
            int head = i / (128 * 128);
            int rem = i - head * 128 * 128;
            int row = rem >> 7, col = rem & 127;
            int k = row >> 4, r = row & 15;
            int wn = col >> 4, c = col & 15;
            int dst = ((head * 8 + k) * 8 + wn) * 256 + r * 16 + c;
            float v = W2[i];
            __half h = __float2half_rn(v);
            d_W2h[dst] = h;
            d_W2l[dst] = __float2half_rn(v - __half2float(h));
        }
    } else {
        for (int i = t; i < NBINS; i += 256) d_binCnt[i] = 0;
        if (t == 0) { d_regE = 0.0f; d_regS = 0.0f; }
    }
}

// ---------------- fp32 -> fp16 conversion (grid-stride, float4 granularity) ---------
__global__ void cvt_kernel(const float* __restrict__ src, __half* __restrict__ dst, int n4) {
    for (int i = blockIdx.x * blockDim.x + threadIdx.x; i < n4; i += gridDim.x * blockDim.x) {
        float4 v = ((const float4*)src)[i];
        __half2 h0 = __floats2half2_rn(v.x, v.y);
        __half2 h1 = __floats2half2_rn(v.z, v.w);
        ((uint2*)dst)[i] = make_uint2(*(unsigned*)&h0, *(unsigned*)&h1);
    }
}

__device__ __forceinline__ float gelu_exact(float x) {
    return x * normcdff(x);
}

// ---------------- selector: split-fp16 WMMA MLP, 64 pts/block ------------------------
// head = headBase + blockIdx.y. head 0: full 3-term MMA + hi/lo h storage;
// heads 1,2: 2-term, hH only. Warp w owns d-columns [w*16, w*16+16), 4 m-tiles.
// dynamic smem (bytes):
//   peH [64][200] : 0     .. 25600
//   peL           : 25600 .. 51200
//   hH  [64][136] : 51200 .. 68608
//   hL            : 68608 .. 86016
//   scratch [8][256]f : 86016 .. 94208
//   outS [64][12]f    : 94208 .. 97280
#define SEL_SMEM_BYTES 97280
__global__ __launch_bounds__(256) void selector_kernel(
    const float* __restrict__ coords,
    const float* __restrict__ b1, const float* __restrict__ b2,
    const float* __restrict__ spaceW3, const float* __restrict__ layerW3,
    const float* __restrict__ scaleW3, int N, int headBase)
{
    extern __shared__ __align__(16) char smraw[];
    __half* peH = (__half*)smraw;
    __half* peL = (__half*)(smraw + 25600);
    __half* hH  = (__half*)(smraw + 51200);
    __half* hL  = (__half*)(smraw + 68608);
    float* scratch = (float*)(smraw + 86016);
    float* outS = (float*)(smraw + 94208);
    __shared__ float redS[64];

    const int t = threadIdx.x;
    const int w = t >> 5;
    const int lane = t & 31;
    const int n0 = blockIdx.x * 64;
    const int head = headBase + blockIdx.y;
    const bool hp = (head == 0);

    // ---- positional encoding, row-major [n][k] ----
    for (int idx = t; idx < 192 * 64; idx += 256) {
        int n = idx & 63;
        int j = idx >> 6;
        int c = j >> 6;
        int r = j & 63;
        int f = r & 31;
        float freq = exp2f((float)f * (8.0f / 31.0f)) * 3.14159265358979323846f;
        float x = (n0 + n < N) ? coords[(n0 + n) * 3 + c] : 0.0f;
        float a = x * freq;
        float v = (r < 32) ? sinf(a) : cosf(a);
        __half h = __float2half_rn(v);
        peH[n * 200 + j] = h;
        if (hp) peL[n * 200 + j] = __float2half_rn(v - __half2float(h));
    }
    __syncthreads();

    const __half* w1h = d_W1h + head * 192 * 128;
    const __half* w1l = d_W1l + head * 192 * 128;
    const __half* w2h = d_W2h + head * 128 * 128;
    const __half* w2l = d_W2l + head * 128 * 128;

    const int bcol = lane & 15;
    const int rbase = lane >> 4;
    const float bias1 = b1[head * 128 + w * 16 + bcol];
    const float bias2 = b2[head * 128 + w * 16 + bcol];
    float* scw = scratch + w * 256;

    // ---- layer 1: h1 = gelu(pe @ W1 + b1) ----
    wmma::fragment<wmma::accumulator, 16, 16, 16, float> acc[4];
    #pragma unroll
    for (int m = 0; m < 4; m++) wmma::fill_fragment(acc[m], 0.0f);

    for (int k = 0; k < 12; k++) {
        wmma::fragment<wmma::matrix_b, 16, 16, 16, __half, wmma::row_major> bh, bl;
        wmma::load_matrix_sync(bh, &w1h[(k * 8 + w) * 256], 16);
        wmma::load_matrix_sync(bl, &w1l[(k * 8 + w) * 256], 16);
        #pragma unroll
        for (int m = 0; m < 4; m++) {
            wmma::fragment<wmma::matrix_a, 16, 16, 16, __half, wmma::row_major> ah;
            wmma::load_matrix_sync(ah, &peH[(m * 16) * 200 + k * 16], 200);
            wmma::mma_sync(acc[m], ah, bh, acc[m]);
            wmma::mma_sync(acc[m], ah, bl, acc[m]);
            if (hp) {
                wmma::fragment<wmma::matrix_a, 16, 16, 16, __half, wmma::row_major> al;
                wmma::load_matrix_sync(al, &peL[(m * 16) * 200 + k * 16], 200);
                wmma::mma_sync(acc[m], al, bh, acc[m]);
            }
        }
    }
    // epilogue 1: bias + gelu + (split) -> hH/hL, via warp-private scratch
    #pragma unroll
    for (int m = 0; m < 4; m++) {
        wmma::store_matrix_sync(scw, acc[m], 16, wmma::mem_row_major);
        __syncwarp();
        #pragma unroll
        for (int q = 0; q < 8; q++) {
            int r_ = rbase + 2 * q;
            float g = gelu_exact(scw[r_ * 16 + bcol] + bias1);
            __half h = __float2half_rn(g);
            int off = (m * 16 + r_) * 136 + w * 16 + bcol;
            hH[off] = h;
            if (hp) hL[off] = __float2half_rn(g - __half2float(h));
        }
        __syncwarp();
    }
    __syncthreads();

    // ---- layer 2: h2 = gelu(h1 @ W2 + b2) ----
    #pragma unroll
    for (int m = 0; m < 4; m++) wmma::fill_fragment(acc[m], 0.0f);
    for (int k = 0; k < 8; k++) {
        wmma::fragment<wmma::matrix_b, 16, 16, 16, __half, wmma::row_major> bh, bl;
        wmma::load_matrix_sync(bh, &w2h[(k * 8 + w) * 256], 16);
        wmma::load_matrix_sync(bl, &w2l[(k * 8 + w) * 256], 16);
        #pragma unroll
        for (int m = 0; m < 4; m++) {
            wmma::fragment<wmma::matrix_a, 16, 16, 16, __half, wmma::row_major> ah;
            wmma::load_matrix_sync(ah, &hH[(m * 16) * 136 + k * 16], 136);
            wmma::mma_sync(acc[m], ah, bh, acc[m]);
            wmma::mma_sync(acc[m], ah, bl, acc[m]);
            if (hp) {
                wmma::fragment<wmma::matrix_a, 16, 16, 16, __half, wmma::row_major> al;
                wmma::load_matrix_sync(al, &hL[(m * 16) * 136 + k * 16], 136);
                wmma::mma_sync(acc[m], al, bh, acc[m]);
            }
        }
    }
    __syncthreads();   // all warps done reading hH/hL before overwrite
    #pragma unroll
    for (int m = 0; m < 4; m++) {
        wmma::store_matrix_sync(scw, acc[m], 16, wmma::mem_row_major);
        __syncwarp();
        #pragma unroll
        for (int q = 0; q < 8; q++) {
            int r_ = rbase + 2 * q;
            float g = gelu_exact(scw[r_ * 16 + bcol] + bias2);
            __half h = __float2half_rn(g);
            int off = (m * 16 + r_) * 136 + w * 16 + bcol;
            hH[off] = h;
            if (hp) hL[off] = __float2half_rn(g - __half2float(h));
        }
        __syncwarp();
    }
    __syncthreads();

    // ---- phase 3: head-specific output + activation ----
    if (head == 0) {
        // h2 reconstructed as hH + hL (fp32-grade)
        if (t < 128) {
            int n = t >> 1, o = t & 1;
            float s = 0.0f;
            for (int k = 0; k < 128; k++)
                s += (__half2float(hH[n * 136 + k]) + __half2float(hL[n * 136 + k]))
                     * spaceW3[k * 2 + o];
            outS[n * 12 + o] = s;
        }
        __syncthreads();
        if (t < 64 && n0 + t < N) {
            float gx = tanhf(outS[t * 12 + 0]);
            float gy = tanhf(outS[t * 12 + 1]);
            float x = (gx + 1.0f) * 8.0f - 0.5f;
            float y = (gy + 1.0f) * 8.0f - 0.5f;
            float x0f = floorf(x), y0f = floorf(y);
            float wx = x - x0f, wy = y - y0f;
            int x0 = (int)x0f, y0 = (int)y0f;
            int x1 = x0 + 1, y1 = y0 + 1;
            float vx0 = (x0 >= 0 && x0 < 16) ? 1.0f : 0.0f;
            float vx1 = (x1 >= 0 && x1 < 16) ? 1.0f : 0.0f;
            float vy0 = (y0 >= 0 && y0 < 16) ? 1.0f : 0.0f;
            float vy1 = (y1 >= 0 && y1 < 16) ? 1.0f : 0.0f;
            int nn = n0 + t;
            d_pwv[nn * 4 + 0] = (1.0f - wx) * (1.0f - wy) * vx0 * vy0;
            d_pwv[nn * 4 + 1] = wx * (1.0f - wy) * vx1 * vy0;
            d_pwv[nn * 4 + 2] = (1.0f - wx) * wy * vx0 * vy1;
            d_pwv[nn * 4 + 3] = wx * wy * vx1 * vy1;
            int bin = (y0 + 1) * 17 + (x0 + 1);      // x0,y0 in [-1,15]
            d_bin[nn] = bin;
            atomicAdd(&d_binCnt[bin], 1);
        }
    } else if (head == 1) {
        for (int idx = t; idx < 768; idx += 256) {
            int n = idx / 12, o = idx - n * 12;
            float s = 0.0f;
            for (int k = 0; k < 128; k++)
                s += __half2float(hH[n * 136 + k]) * layerW3[k * 12 + o];
            outS[n * 12 + o] = s;
        }
        __syncthreads();
        if (t < 64) {
            float ent = 0.0f;
            if (n0 + t < N) {
                float m = -1e30f;
                #pragma unroll
                for (int o = 0; o < 12; o++) m = fmaxf(m, outS[t * 12 + o]);
                float e[12], sum = 0.0f;
                #pragma unroll
                for (int o = 0; o < 12; o++) { e[o] = expf(outS[t * 12 + o] - m); sum += e[o]; }
                float inv = 1.0f / sum;
                #pragma unroll
                for (int o = 0; o < 12; o++) {
                    float p = e[o] * inv;
                    d_wl[(n0 + t) * 12 + o] = p;
                    ent += p * logf(p + 1e-8f);
                }
            }
            redS[t] = ent;
        }
        __syncthreads();
        if (t == 0) {
            float se = 0.0f;
            #pragma unroll
            for (int i = 0; i < 64; i++) se += redS[i];
            atomicAdd(&d_regE, se);
        }
    } else {
        if (t < 64) {
            float s = 0.0f;
            for (int k = 0; k < 128; k++)
                s += __half2float(hH[t * 136 + k]) * scaleW3[k];
            float pen = 0.0f;
            if (n0 + t < N) {
                float sg = 1.0f / (1.0f + expf(-s));
                d_sscale[n0 + t] = sg;
                float dd = sg - 0.5f;
                pen = dd * dd;
            }
            redS[t] = pen;
        }
        __syncthreads();
        if (t == 0) {
            float sp = 0.0f;
            #pragma unroll
            for (int i = 0; i < 64; i++) sp += redS[i];
            atomicAdd(&d_regS, sp);
        }
    }
}

// ---------------- scan: parallel prefix over bins, build chunks ----------------------
__global__ __launch_bounds__(512) void scan_kernel(float* __restrict__ out, int N, int out_size) {
    __shared__ int cS[NBINS];
    __shared__ int sS[NBINS];
    __shared__ int chS[NBINS];
    int t = threadIdx.x;
    if (t < NBINS) {
        cS[t] = d_binCnt[t];
        sS[t] = cS[t];
        chS[t] = (cS[t] + CHSZ - 1) / CHSZ;
    }
    __syncthreads();
    for (int off = 1; off < NBINS; off <<= 1) {
        int v1 = 0, v2 = 0;
        if (t < NBINS && t >= off) { v1 = sS[t - off]; v2 = chS[t - off]; }
        __syncthreads();
        if (t < NBINS && t >= off) { sS[t] += v1; chS[t] += v2; }
        __syncthreads();
    }
    if (t < NBINS) {
        int cnt = cS[t];
        int start = sS[t] - cnt;
        int choff = chS[t] - (cnt + CHSZ - 1) / CHSZ;
        d_binStart[t] = start;
        d_binCursor[t] = 0;
        int off = 0, j = 0;
        while (off < cnt) {
            int c = min(CHSZ, cnt - off);
            d_chunks[choff + j] = make_uint2((unsigned)(t | (c << 16)), (unsigned)(start + off));
            off += CHSZ;
            j++;
        }
        if (t == NBINS - 1) d_numChunks = chS[t];
    }
}

// ---------------- reg scalar writer (needs heads 1,2 done) ---------------------------
__global__ void reg_kernel(float* __restrict__ out, int N, int out_size) {
    if (out_size > BB * N) {
        float reg = d_regE / ((float)N * logf(12.0f)) + d_regS / (float)N;
        out[BB * N] = reg;
    }
}

// ---------------- scatter: point id -> ordered-by-bin list -------------------------
__global__ __launch_bounds__(256) void scatter_kernel(int N) {
    __shared__ int sCnt[NBINS];
    __shared__ int sBase[NBINS];
    int t = threadIdx.x;
    for (int i = t; i < NBINS; i += 256) sCnt[i] = 0;
    __syncthreads();
    int n = blockIdx.x * 256 + t;
    int bin = -1, loc = 0;
    if (n < N) {
        bin = d_bin[n];
        loc = atomicAdd(&sCnt[bin], 1);
    }
    __syncthreads();
    for (int i = t; i < NBINS; i += 256)
        if (sCnt[i] > 0) sBase[i] = atomicAdd(&d_binCursor[i], sCnt[i]);
    __syncthreads();
    if (n < N) d_order[d_binStart[bin] + sBase[bin] + loc] = n;
}

// ---------------- gb[l,b,d] (fp16 out), grid (48,4), float4 lane loads ---------------
__global__ __launch_bounds__(128) void gb_kernel(
    const float* __restrict__ gt, const float* __restrict__ gw)
{
    int lb = blockIdx.x;
    int dg = blockIdx.y;                // d group of 32
    int l = lb >> 2, b = lb & 3;
    __shared__ __align__(16) float gS[CC];
    int t = threadIdx.x;
    for (int i = t; i < CC; i += 128) gS[i] = gt[(l * BB + b) * CC + i];
    __syncthreads();
    int warp = t >> 5, lane = t & 31;
    #pragma unroll
    for (int dd = 0; dd < 8; dd++) {
        int d = dg * 32 + warp * 8 + dd;
        const float4* wr = (const float4*)(gw + ((size_t)(l * DD + d)) * CC);
        const float4* gs4 = (const float4*)gS;
        float s = 0.0f;
        #pragma unroll
        for (int i = 0; i < 6; i++) {
            float4 wv = wr[lane + i * 32];
            float4 gv = gs4[lane + i * 32];
            s += wv.x * gv.x + wv.y * gv.y + wv.z * gv.z + wv.w * gv.w;
        }
        #pragma unroll
        for (int o = 16; o; o >>= 1) s += __shfl_xor_sync(0xFFFFFFFFu, s, o);
        if (lane == 0) d_gb_h[(l * BB + b) * DD + d] = __float2half(s);
    }
}

// ---------------- conv via WMMA fp16 tensor cores, 384 blocks ------------------------
// block = (lb, p-tile of 32). warp w owns d columns [w*16, w*16+16), 2 m-tiles.
__global__ __launch_bounds__(256) void conv_kernel(const float* __restrict__ lt) {
    __shared__ __align__(16) __half aS[64 * 40];     // [c][px], ldA = 40
    __shared__ __align__(16) __half bS[128 * 72];    // [d][c], ldB = 72
    __shared__ __align__(16) float scratch[8][256];

    int bid = blockIdx.x;
    int lb = bid >> 3;
    int p0 = (bid & 7) * 32;
    int l = lb >> 2;

    const int t = threadIdx.x;
    const int w = t >> 5;
    const int lane = t & 31;

    wmma::fragment<wmma::accumulator, 16, 16, 16, float> acc[2];
    wmma::fill_fragment(acc[0], 0.0f);
    wmma::fill_fragment(acc[1], 0.0f);

    for (int c0 = 0; c0 < CC; c0 += 64) {
        // stage A from fp32 global, convert inline: 64 c-rows x 32 px (float4 = 4 px)
        for (int idx = t; idx < 512; idx += 256) {
            int row = idx >> 3, g = idx & 7;
            float4 v = *(const float4*)&lt[((size_t)lb * CC + c0 + row) * HWN + p0 + g * 4];
            __half2 h0 = __floats2half2_rn(v.x, v.y);
            __half2 h1 = __floats2half2_rn(v.z, v.w);
            *(uint2*)&aS[row * 40 + g * 4] = make_uint2(*(unsigned*)&h0, *(unsigned*)&h1);
        }
        for (int idx = t; idx < 1024; idx += 256) {
            int row = idx >> 3, g = idx & 7;
            *(uint4*)&bS[row * 72 + g * 8] =
                *(const uint4*)&d_cw_h[((size_t)(l * DD) + row) * CC + c0 + g * 8];
        }
        __syncthreads();

        #pragma unroll
        for (int kk = 0; kk < 4; kk++) {
            wmma::fragment<wmma::matrix_a, 16, 16, 16, __half, wmma::col_major> af[2];
            wmma::fragment<wmma::matrix_b, 16, 16, 16, __half, wmma::col_major> bf;
            #pragma unroll
            for (int i = 0; i < 2; i++)
                wmma::load_matrix_sync(af[i], &aS[(kk * 16) * 40 + i * 16], 40);
            wmma::load_matrix_sync(bf, &bS[(w * 16) * 72 + kk * 16], 72);
            #pragma unroll
            for (int i = 0; i < 2; i++)
                wmma::mma_sync(acc[i], af[i], bf, acc[i]);
        }
        __syncthreads();
    }

    #pragma unroll
    for (int i = 0; i < 2; i++) {
        wmma::store_matrix_sync(&scratch[w][0], acc[i], 16, wmma::mem_row_major);
        __syncwarp();
        int r = lane >> 1;
        int cbase = (lane & 1) * 8;
        __align__(16) __half2 hv[4];
        #pragma unroll
        for (int q = 0; q < 4; q++) {
            float a = scratch[w][r * 16 + cbase + 2 * q];
            float bq = scratch[w][r * 16 + cbase + 2 * q + 1];
            hv[q] = __floats2half2_rn(a, bq);
        }
        size_t px = (size_t)lb * HWN + p0 + i * 16 + r;
        *(uint4*)&d_feat_h[px * DD + w * 16 + cbase] = *(uint4*)hv;
        __syncwarp();
    }
}

// ---------------- final: binned GEMM via tensor cores --------------------------------
#define FINAL_SMEM 98304
__global__ __launch_bounds__(256) void final_kernel(
    const float* __restrict__ ow, const float* __restrict__ ob,
    float* __restrict__ out, int N)
{
    extern __shared__ __align__(16) char fraw[];
    __half* featG = (__half*)fraw;                 // [b][k][136]
    __half* coefH = (__half*)(fraw + 69632);       // [p][72]
    __half* coefL = (__half*)(fraw + 78848);
    float* scratch = (float*)(fraw + 88064);       // [w][256] (16x16 tile, ld 16)
    float* partial = (float*)(fraw + 96256);       // [p][8]
    __shared__ int nidS[64];
    __shared__ float obS[64];

    int cid = blockIdx.x;
    if (cid >= d_numChunks) return;
    uint2 ch = d_chunks[cid];
    int bin = (int)(ch.x & 0xFFFF);
    int cnt = (int)(ch.x >> 16);
    int start = (int)ch.y;

    int x0 = (bin % 17) - 1;
    int y0 = (bin / 17) - 1;
    int cx0 = min(max(x0, 0), 15), cx1 = min(max(x0 + 1, 0), 15);
    int cy0 = min(max(y0, 0), 15), cy1 = min(max(y0 + 1, 0), 15);
    int pix[4] = {cy0 * 16 + cx0, cy0 * 16 + cx1, cy1 * 16 + cx0, cy1 * 16 + cx1};

    const int t = threadIdx.x;
    const int w = t >> 5;
    const int lane = t & 31;

    for (int idx = t; idx < 4 * 64 * 16; idx += 256) {
        int b = idx >> 10;
        int rem = idx & 1023;
        int k = rem >> 4, g = rem & 15;
        uint4 v;
        if (k < 48) {
            int l = k >> 2, c = k & 3;
            v = *(const uint4*)&d_feat_h[((size_t)(l * 4 + b) * HWN + pix[c]) * DD + g * 8];
        } else if (k < 60) {
            int l = k - 48;
            v = *(const uint4*)&d_gb_h[(l * 4 + b) * DD + g * 8];
        } else {
            v = make_uint4(0, 0, 0, 0);
        }
        *(uint4*)&featG[(b * 64 + k) * 136 + g * 8] = v;
    }

    if (t < 64) {
        if (t < cnt) {
            int n = d_order[start + t];
            nidS[t] = n;
            obS[t] = ob[n];
            float s = d_sscale[n];
            float os = 1.0f - s;
            float pw[4];
            #pragma unroll
            for (int c = 0; c < 4; c++) pw[c] = d_pwv[n * 4 + c];
            #pragma unroll
            for (int l = 0; l < 12; l++) {
                float cl = d_wl[n * 12 + l];
                #pragma unroll
                for (int c = 0; c < 4; c++) {
                    float v = os * cl * pw[c];
                    __half h = __float2half_rn(v);
                    coefH[t * 72 + l * 4 + c] = h;
                    coefL[t * 72 + l * 4 + c] = __float2half_rn(v - __half2float(h));
                }
                float vg = s * cl;
                __half hg = __float2half_rn(vg);
                coefH[t * 72 + 48 + l] = hg;
                coefL[t * 72 + 48 + l] = __float2half_rn(vg - __half2float(hg));
            }
            #pragma unroll
            for (int k = 60; k < 64; k++) {
                coefH[t * 72 + k] = __float2half(0.0f);
                coefL[t * 72 + k] = __float2half(0.0f);
            }
        } else {
            for (int k = 0; k < 64; k++) {
                coefH[t * 72 + k] = __float2half(0.0f);
                coefL[t * 72 + k] = __float2half(0.0f);
            }
        }
    }
    __syncthreads();

    for (int b = 0; b < 4; b++) {
        const __half* Bb = featG + b * 64 * 136;
        wmma::fragment<wmma::accumulator, 16, 16, 16, float> acc[4];
        #pragma unroll
        for (int m = 0; m < 4; m++) wmma::fill_fragment(acc[m], 0.0f);

        #pragma unroll
        for (int kt = 0; kt < 4; kt++) {
            wmma::fragment<wmma::matrix_b, 16, 16, 16, __half, wmma::row_major> bf;
            wmma::load_matrix_sync(bf, &Bb[(kt * 16) * 136 + w * 16], 136);
            #pragma unroll
            for (int m = 0; m < 4; m++) {
                wmma::fragment<wmma::matrix_a, 16, 16, 16, __half, wmma::row_major> af;
                wmma::load_matrix_sync(af, &coefH[(m * 16) * 72 + kt * 16], 72);
                wmma::mma_sync(acc[m], af, bf, acc[m]);
            }
            #pragma unroll
            for (int m = 0; m < 4; m++) {
                wmma::fragment<wmma::matrix_a, 16, 16, 16, __half, wmma::row_major> af;
                wmma::load_matrix_sync(af, &coefL[(m * 16) * 72 + kt * 16], 72);
                wmma::mma_sync(acc[m], af, bf, acc[m]);
            }
        }

        float* scw = scratch + w * 256;
        #pragma unroll
        for (int m = 0; m < 4; m++) {
            wmma::store_matrix_sync(scw, acc[m], 16, wmma::mem_row_major);
            __syncwarp();
            int r = lane >> 1;
            int p = m * 16 + r;
            float sum = 0.0f;
            if (p < cnt) {
                int dbase = w * 16 + (lane & 1) * 8;
                const float* owp = ow + (size_t)nidS[p] * DD + dbase;
                float4 o0 = *(const float4*)owp;
                float4 o1 = *(const float4*)(owp + 4);
                const float* vp = scw + r * 16 + (lane & 1) * 8;
                sum = vp[0] * o0.x + vp[1] * o0.y + vp[2] * o0.z + vp[3] * o0.w
                    + vp[4] * o1.x + vp[5] * o1.y + vp[6] * o1.z + vp[7] * o1.w;
            }
            sum += __shfl_xor_sync(0xFFFFFFFFu, sum, 1);
            if ((lane & 1) == 0 && p < cnt) partial[p * 8 + w] = sum;
            __syncwarp();
        }
        __syncthreads();

        if (t < 64 && t < cnt) {
            float y = 0.0f;
            #pragma unroll
            for (int ww = 0; ww < 8; ww++) y += partial[t * 8 + ww];
            out[b * N + nidS[t]] = y * (1.0f / 128.0f) + obS[t];
        }
        __syncthreads();
    }
}

// ---------------- launch ----------------
extern "C" void kernel_launch(void* const* d_in, const int* in_sizes, int n_in,
                              void* d_out, int out_size) {
    const float* lt      = (const float*)d_in[0];
    const float* gt      = (const float*)d_in[1];
    const float* coords  = (const float*)d_in[2];
    const float* conv_w  = (const float*)d_in[3];
    const float* glob_w  = (const float*)d_in[4];
    const float* W1      = (const float*)d_in[5];
    const float* b1      = (const float*)d_in[6];
    const float* W2      = (const float*)d_in[7];
    const float* b2      = (const float*)d_in[8];
    const float* spaceW3 = (const float*)d_in[9];
    const float* layerW3 = (const float*)d_in[10];
    const float* scaleW3 = (const float*)d_in[11];
    const float* ow      = (const float*)d_in[12];
    const float* ob      = (const float*)d_in[13];
    int N = in_sizes[2] / 3;
    float* out = (float*)d_out;

    __half* cw_h; cudaGetSymbolAddress((void**)&cw_h, d_cw_h);

    static cudaStream_t s2 = nullptr, s3 = nullptr;
    static cudaEvent_t evFork = nullptr, evJ2 = nullptr, evJ3 = nullptr;
    if (s2 == nullptr) {
        cudaStreamCreateWithFlags(&s2, cudaStreamNonBlocking);
        cudaStreamCreateWithFlags(&s3, cudaStreamNonBlocking);
        cudaEventCreateWithFlags(&evFork, cudaEventDisableTiming);
        cudaEventCreateWithFlags(&evJ2, cudaEventDisableTiming);
        cudaEventCreateWithFlags(&evJ3, cudaEventDisableTiming);
        cudaFuncSetAttribute(selector_kernel,
                             cudaFuncAttributeMaxDynamicSharedMemorySize, SEL_SMEM_BYTES);
        cudaFuncSetAttribute(final_kernel,
                             cudaFuncAttributeMaxDynamicSharedMemorySize, FINAL_SMEM);
    }

    int nblk = (N + 63) / 64;

    prep_kernel<<<385, 256>>>(W1, W2);
    cudaEventRecord(evFork, 0);
    cudaStreamWaitEvent(s2, evFork, 0);
    cudaStreamWaitEvent(s3, evFork, 0);

    // s2: conv chain (independent until final)
    cvt_kernel<<<288, 256, 0, s2>>>(conv_w, cw_h, LL * DD * CC / 4);
    gb_kernel<<<dim3(48, 4), 128, 0, s2>>>(gt, glob_w);
    conv_kernel<<<384, 256, 0, s2>>>(lt);
    cudaEventRecord(evJ2, s2);

    // s3: heads 1,2 (2-term) -> reg scalar
    selector_kernel<<<dim3(nblk, 2), 256, SEL_SMEM_BYTES, s3>>>(
        coords, b1, b2, spaceW3, layerW3, scaleW3, N, 1);
    reg_kernel<<<1, 1, 0, s3>>>(out, N, out_size);
    cudaEventRecord(evJ3, s3);

    // main: head 0 (3-term) -> scan -> scatter
    selector_kernel<<<dim3(nblk, 1), 256, SEL_SMEM_BYTES>>>(
        coords, b1, b2, spaceW3, layerW3, scaleW3, N, 0);
    scan_kernel<<<1, 512>>>(out, N, out_size);
    scatter_kernel<<<(N + 255) / 256, 256>>>(N);

    cudaStreamWaitEvent(0, evJ2, 0);
    cudaStreamWaitEvent(0, evJ3, 0);
    final_kernel<<<NBINS + (N + CHSZ - 1) / CHSZ, 256, FINAL_SMEM>>>(ow, ob, out, N);
}

// round 16
// speedup vs baseline: 1.0862x; 1.0862x over previous
#include <cuda_runtime.h>
#include <cuda_fp16.h>
#include <mma.h>
#include <math.h>

using namespace nvcuda;

#define LL 12
#define BB 4
#define CC 768
#define DD 128
#define HWN 256
#define MAXN 30016
#define NBINS 289          // 17 x 17 possible (x0,y0) patches
#define MAXCHUNK 1024
#define CHSZ 64

// ---------------- scratch (static device arrays; no cudaMalloc) ----------------
__device__ __half d_cw_h[LL * DD * CC];          // fp16 copy of conv_w
__device__ __half d_feat_h[LL * BB * HWN * DD];  // [lb][pix][d], fp16, 3.15 MB
__device__ __half d_gb_h[LL * BB * DD];          // [lb][d] fp16
// W1/W2 in fragment-tiled layout: [head][k][wn][16*16], tile ld = 16
__device__ __half d_W1h[3 * 192 * 128];
__device__ __half d_W1l[3 * 192 * 128];
__device__ __half d_W2h[3 * 128 * 128];
__device__ __half d_W2l[3 * 128 * 128];
__device__ float d_pwv[MAXN * 4];
__device__ float d_wl[MAXN * LL];
__device__ float d_sscale[MAXN];
__device__ int   d_bin[MAXN];
__device__ int   d_binCnt[NBINS];
__device__ int   d_binStart[NBINS];
__device__ int   d_binCursor[NBINS];
__device__ int   d_order[MAXN];
__device__ uint2 d_chunks[MAXCHUNK];   // {bin | cnt<<16, start}
__device__ int   d_numChunks;
__device__ float d_regE;
__device__ float d_regS;

// ---------------- prep: W1/W2 hi-lo split into tiled layout + init ------------------
__global__ __launch_bounds__(256) void prep_kernel(
    const float* __restrict__ W1, const float* __restrict__ W2)
{
    int b = blockIdx.x, t = threadIdx.x;
    if (b < 288) {
        int n = 3 * 192 * 128;
        for (int i = b * 256 + t; i < n; i += 288 * 256) {
            int head = i / (192 * 128);
            int rem = i - head * 192 * 128;
            int row = rem >> 7, col = rem & 127;     // row 0..191, col 0..127
            int k = row >> 4, r = row & 15;
            int wn = col >> 4, c = col & 15;
            int dst = ((head * 12 + k) * 8 + wn) * 256 + r * 16 + c;
            float v = W1[i];
            __half h = __float2half_rn(v);
            d_W1h[dst] = h;
            d_W1l[dst] = __float2half_rn(v - __half2float(h));
        }
    } else if (b < 384) {
        int n = 3 * 128 * 128;
        for (int i = (b - 288) * 256 + t; i < n; i += 96 * 256) {
            int head = i / (128 * 128);
            int rem = i - head * 128 * 128;
            int row = rem >> 7, col = rem & 127;
            int k = row >> 4, r = row & 15;
            int wn = col >> 4, c = col & 15;
            int dst = ((head * 8 + k) * 8 + wn) * 256 + r * 16 + c;
            float v = W2[i];
            __half h = __float2half_rn(v);
            d_W2h[dst] = h;
            d_W2l[dst] = __float2half_rn(v - __half2float(h));
        }
    } else {
        for (int i = t; i < NBINS; i += 256) d_binCnt[i] = 0;
        if (t == 0) { d_regE = 0.0f; d_regS = 0.0f; }
    }
}

// ---------------- fp32 -> fp16 conversion (grid-stride, float4 granularity) ---------
__global__ void cvt_kernel(const float* __restrict__ src, __half* __restrict__ dst, int n4) {
    for (int i = blockIdx.x * blockDim.x + threadIdx.x; i < n4; i += gridDim.x * blockDim.x) {
        float4 v = ((const float4*)src)[i];
        __half2 h0 = __floats2half2_rn(v.x, v.y);
        __half2 h1 = __floats2half2_rn(v.z, v.w);
        ((uint2*)dst)[i] = make_uint2(*(unsigned*)&h0, *(unsigned*)&h1);
    }
}

__device__ __forceinline__ float gelu_exact(float x) {
    return x * normcdff(x);
}

// ---------------- selector: split-fp16 WMMA MLP, 32 pts/block (R14 shape) ------------
// head = headBase + blockIdx.y. head 0: full 3-term MMA; heads 1,2: 2-term.
#define SEL_SMEM_BYTES 59904
__global__ __launch_bounds__(256) void selector_kernel(
    const float* __restrict__ coords,
    const float* __restrict__ b1, const float* __restrict__ b2,
    const float* __restrict__ spaceW3, const float* __restrict__ layerW3,
    const float* __restrict__ scaleW3, int N, int headBase)
{
    extern __shared__ __align__(16) char smraw[];
    __half* peH = (__half*)smraw;
    __half* peL = peH + 32 * 200;
    __half* hH  = peH + 12800;
    __half* hL  = peH + 17152;
    float*  t32 = (float*)(smraw + 43008);

    __shared__ float outS[32][12];
    __shared__ float redS[32];

    const int t = threadIdx.x;
    const int w = t >> 5;              // warp = n-tile (16 cols of 128)
    const int n0 = blockIdx.x * 32;
    const int head = headBase + blockIdx.y;
    const bool hp = (head == 0);       // high-precision path

    // ---- positional encoding, row-major [n][k] ----
    for (int idx = t; idx < 192 * 32; idx += 256) {
        int n = idx & 31;
        int j = idx >> 5;
        int c = j >> 6;
        int r = j & 63;
        int f = r & 31;
        float freq = exp2f((float)f * (8.0f / 31.0f)) * 3.14159265358979323846f;
        float x = (n0 + n < N) ? coords[(n0 + n) * 3 + c] : 0.0f;
        float a = x * freq;
        float v = (r < 32) ? sinf(a) : cosf(a);
        __half h = __float2half_rn(v);
        peH[n * 200 + j] = h;
        if (hp) peL[n * 200 + j] = __float2half_rn(v - __half2float(h));
    }
    __syncthreads();

    const __half* w1h = d_W1h + head * 192 * 128;
    const __half* w1l = d_W1l + head * 192 * 128;
    const __half* w2h = d_W2h + head * 128 * 128;
    const __half* w2l = d_W2l + head * 128 * 128;

    // ---- layer 1: h1 = gelu(pe @ W1 + b1) ----
    wmma::fragment<wmma::accumulator, 16, 16, 16, float> acc[2];
    wmma::fill_fragment(acc[0], 0.0f);
    wmma::fill_fragment(acc[1], 0.0f);

    for (int k = 0; k < 12; k++) {
        wmma::fragment<wmma::matrix_a, 16, 16, 16, __half, wmma::row_major> ah[2];
        wmma::fragment<wmma::matrix_b, 16, 16, 16, __half, wmma::row_major> bh, bl;
        wmma::load_matrix_sync(ah[0], &peH[k * 16], 200);
        wmma::load_matrix_sync(ah[1], &peH[16 * 200 + k * 16], 200);
        wmma::load_matrix_sync(bh, &w1h[(k * 8 + w) * 256], 16);
        wmma::load_matrix_sync(bl, &w1l[(k * 8 + w) * 256], 16);
        #pragma unroll
        for (int m = 0; m < 2; m++) {
            wmma::mma_sync(acc[m], ah[m], bh, acc[m]);
            wmma::mma_sync(acc[m], ah[m], bl, acc[m]);
        }
        if (hp) {
            wmma::fragment<wmma::matrix_a, 16, 16, 16, __half, wmma::row_major> al[2];
            wmma::load_matrix_sync(al[0], &peL[k * 16], 200);
            wmma::load_matrix_sync(al[1], &peL[16 * 200 + k * 16], 200);
            #pragma unroll
            for (int m = 0; m < 2; m++)
                wmma::mma_sync(acc[m], al[m], bh, acc[m]);
        }
    }
    wmma::store_matrix_sync(&t32[w * 16], acc[0], 132, wmma::mem_row_major);
    wmma::store_matrix_sync(&t32[16 * 132 + w * 16], acc[1], 132, wmma::mem_row_major);
    __syncthreads();

    for (int idx = t; idx < 32 * 128; idx += 256) {
        int n = idx >> 7, d = idx & 127;
        float g = gelu_exact(t32[n * 132 + d] + b1[head * 128 + d]);
        __half h = __float2half_rn(g);
        hH[n * 136 + d] = h;
        if (hp) hL[n * 136 + d] = __float2half_rn(g - __half2float(h));
    }
    __syncthreads();

    // ---- layer 2: h2 = gelu(h1 @ W2 + b2) ----
    wmma::fill_fragment(acc[0], 0.0f);
    wmma::fill_fragment(acc[1], 0.0f);
    for (int k = 0; k < 8; k++) {
        wmma::fragment<wmma::matrix_a, 16, 16, 16, __half, wmma::row_major> ah[2];
        wmma::fragment<wmma::matrix_b, 16, 16, 16, __half, wmma::row_major> bh, bl;
        wmma::load_matrix_sync(ah[0], &hH[k * 16], 136);
        wmma::load_matrix_sync(ah[1], &hH[16 * 136 + k * 16], 136);
        wmma::load_matrix_sync(bh, &w2h[(k * 8 + w) * 256], 16);
        wmma::load_matrix_sync(bl, &w2l[(k * 8 + w) * 256], 16);
        #pragma unroll
        for (int m = 0; m < 2; m++) {
            wmma::mma_sync(acc[m], ah[m], bh, acc[m]);
            wmma::mma_sync(acc[m], ah[m], bl, acc[m]);
        }
        if (hp) {
            wmma::fragment<wmma::matrix_a, 16, 16, 16, __half, wmma::row_major> al[2];
            wmma::load_matrix_sync(al[0], &hL[k * 16], 136);
            wmma::load_matrix_sync(al[1], &hL[16 * 136 + k * 16], 136);
            #pragma unroll
            for (int m = 0; m < 2; m++)
                wmma::mma_sync(acc[m], al[m], bh, acc[m]);
        }
    }
    wmma::store_matrix_sync(&t32[w * 16], acc[0], 132, wmma::mem_row_major);
    wmma::store_matrix_sync(&t32[16 * 132 + w * 16], acc[1], 132, wmma::mem_row_major);
    __syncthreads();

    for (int idx = t; idx < 32 * 128; idx += 256) {
        int n = idx >> 7, d = idx & 127;
        t32[n * 132 + d] = gelu_exact(t32[n * 132 + d] + b2[head * 128 + d]);
    }
    __syncthreads();

    // ---- phase 3: head-specific output + activation ----
    if (head == 0) {
        for (int idx = t; idx < 64; idx += 256) {
            int n = idx >> 1, o = idx & 1;
            float s = 0.0f;
            for (int k = 0; k < 128; k++) s += t32[n * 132 + k] * spaceW3[k * 2 + o];
            outS[n][o] = s;
        }
        __syncthreads();
        if (t < 32 && n0 + t < N) {
            float gx = tanhf(outS[t][0]);
            float gy = tanhf(outS[t][1]);
            float x = (gx + 1.0f) * 8.0f - 0.5f;
            float y = (gy + 1.0f) * 8.0f - 0.5f;
            float x0f = floorf(x), y0f = floorf(y);
            float wx = x - x0f, wy = y - y0f;
            int x0 = (int)x0f, y0 = (int)y0f;
            int x1 = x0 + 1, y1 = y0 + 1;
            float vx0 = (x0 >= 0 && x0 < 16) ? 1.0f : 0.0f;
            float vx1 = (x1 >= 0 && x1 < 16) ? 1.0f : 0.0f;
            float vy0 = (y0 >= 0 && y0 < 16) ? 1.0f : 0.0f;
            float vy1 = (y1 >= 0 && y1 < 16) ? 1.0f : 0.0f;
            int nn = n0 + t;
            d_pwv[nn * 4 + 0] = (1.0f - wx) * (1.0f - wy) * vx0 * vy0;
            d_pwv[nn * 4 + 1] = wx * (1.0f - wy) * vx1 * vy0;
            d_pwv[nn * 4 + 2] = (1.0f - wx) * wy * vx0 * vy1;
            d_pwv[nn * 4 + 3] = wx * wy * vx1 * vy1;
            int bin = (y0 + 1) * 17 + (x0 + 1);      // x0,y0 in [-1,15]
            d_bin[nn] = bin;
            atomicAdd(&d_binCnt[bin], 1);
        }
    } else if (head == 1) {
        for (int idx = t; idx < 384; idx += 256) {
            int n = idx / 12, o = idx - n * 12;
            float s = 0.0f;
            for (int k = 0; k < 128; k++) s += t32[n * 132 + k] * layerW3[k * 12 + o];
            outS[n][o] = s;
        }
        __syncthreads();
        if (t < 32) {
            float ent = 0.0f;
            if (n0 + t < N) {
                float m = -1e30f;
                #pragma unroll
                for (int o = 0; o < 12; o++) m = fmaxf(m, outS[t][o]);
                float e[12], sum = 0.0f;
                #pragma unroll
                for (int o = 0; o < 12; o++) { e[o] = expf(outS[t][o] - m); sum += e[o]; }
                float inv = 1.0f / sum;
                #pragma unroll
                for (int o = 0; o < 12; o++) {
                    float p = e[o] * inv;
                    d_wl[(n0 + t) * 12 + o] = p;
                    ent += p * logf(p + 1e-8f);
                }
            }
            redS[t] = ent;
        }
        __syncthreads();
        if (t == 0) {
            float se = 0.0f;
            #pragma unroll
            for (int i = 0; i < 32; i++) se += redS[i];
            atomicAdd(&d_regE, se);
        }
    } else {
        for (int idx = t; idx < 32; idx += 256) {
            float s = 0.0f;
            for (int k = 0; k < 128; k++) s += t32[idx * 132 + k] * scaleW3[k];
            outS[idx][0] = s;
        }
        __syncthreads();
        if (t < 32) {
            float pen = 0.0f;
            if (n0 + t < N) {
                float sg = 1.0f / (1.0f + expf(-outS[t][0]));
                d_sscale[n0 + t] = sg;
                float dd = sg - 0.5f;
                pen = dd * dd;
            }
            redS[t] = pen;
        }
        __syncthreads();
        if (t == 0) {
            float sp = 0.0f;
            #pragma unroll
            for (int i = 0; i < 32; i++) sp += redS[i];
            atomicAdd(&d_regS, sp);
        }
    }
}

// ---------------- scan: parallel prefix over bins, build chunks ----------------------
__global__ __launch_bounds__(512) void scan_kernel(float* __restrict__ out, int N, int out_size) {
    __shared__ int cS[NBINS];
    __shared__ int sS[NBINS];
    __shared__ int chS[NBINS];
    int t = threadIdx.x;
    if (t < NBINS) {
        cS[t] = d_binCnt[t];
        sS[t] = cS[t];
        chS[t] = (cS[t] + CHSZ - 1) / CHSZ;
    }
    __syncthreads();
    for (int off = 1; off < NBINS; off <<= 1) {
        int v1 = 0, v2 = 0;
        if (t < NBINS && t >= off) { v1 = sS[t - off]; v2 = chS[t - off]; }
        __syncthreads();
        if (t < NBINS && t >= off) { sS[t] += v1; chS[t] += v2; }
        __syncthreads();
    }
    if (t < NBINS) {
        int cnt = cS[t];
        int start = sS[t] - cnt;
        int choff = chS[t] - (cnt + CHSZ - 1) / CHSZ;
        d_binStart[t] = start;
        d_binCursor[t] = 0;
        int off = 0, j = 0;
        while (off < cnt) {
            int c = min(CHSZ, cnt - off);
            d_chunks[choff + j] = make_uint2((unsigned)(t | (c << 16)), (unsigned)(start + off));
            off += CHSZ;
            j++;
        }
        if (t == NBINS - 1) d_numChunks = chS[t];
    }
}

// ---------------- reg scalar writer (needs heads 1,2 done) ---------------------------
__global__ void reg_kernel(float* __restrict__ out, int N, int out_size) {
    if (out_size > BB * N) {
        float reg = d_regE / ((float)N * logf(12.0f)) + d_regS / (float)N;
        out[BB * N] = reg;
    }
}

// ---------------- scatter: point id -> ordered-by-bin list -------------------------
__global__ __launch_bounds__(256) void scatter_kernel(int N) {
    __shared__ int sCnt[NBINS];
    __shared__ int sBase[NBINS];
    int t = threadIdx.x;
    for (int i = t; i < NBINS; i += 256) sCnt[i] = 0;
    __syncthreads();
    int n = blockIdx.x * 256 + t;
    int bin = -1, loc = 0;
    if (n < N) {
        bin = d_bin[n];
        loc = atomicAdd(&sCnt[bin], 1);
    }
    __syncthreads();
    for (int i = t; i < NBINS; i += 256)
        if (sCnt[i] > 0) sBase[i] = atomicAdd(&d_binCursor[i], sCnt[i]);
    __syncthreads();
    if (n < N) d_order[d_binStart[bin] + sBase[bin] + loc] = n;
}

// ---------------- gb[l,b,d] (fp16 out), grid (48,4), float4 lane loads ---------------
__global__ __launch_bounds__(128) void gb_kernel(
    const float* __restrict__ gt, const float* __restrict__ gw)
{
    int lb = blockIdx.x;
    int dg = blockIdx.y;                // d group of 32
    int l = lb >> 2, b = lb & 3;
    __shared__ __align__(16) float gS[CC];
    int t = threadIdx.x;
    for (int i = t; i < CC; i += 128) gS[i] = gt[(l * BB + b) * CC + i];
    __syncthreads();
    int warp = t >> 5, lane = t & 31;
    #pragma unroll
    for (int dd = 0; dd < 8; dd++) {
        int d = dg * 32 + warp * 8 + dd;
        const float4* wr = (const float4*)(gw + ((size_t)(l * DD + d)) * CC);
        const float4* gs4 = (const float4*)gS;
        float s = 0.0f;
        #pragma unroll
        for (int i = 0; i < 6; i++) {
            float4 wv = wr[lane + i * 32];
            float4 gv = gs4[lane + i * 32];
            s += wv.x * gv.x + wv.y * gv.y + wv.z * gv.z + wv.w * gv.w;
        }
        #pragma unroll
        for (int o = 16; o; o >>= 1) s += __shfl_xor_sync(0xFFFFFFFFu, s, o);
        if (lane == 0) d_gb_h[(l * BB + b) * DD + d] = __float2half(s);
    }
}

// ---------------- conv via WMMA fp16 tensor cores, 384 blocks ------------------------
__global__ __launch_bounds__(256) void conv_kernel(const float* __restrict__ lt) {
    __shared__ __align__(16) __half aS[64 * 40];     // [c][px], ldA = 40
    __shared__ __align__(16) __half bS[128 * 72];    // [d][c], ldB = 72
    __shared__ __align__(16) float scratch[8][256];

    int bid = blockIdx.x;
    int lb = bid >> 3;
    int p0 = (bid & 7) * 32;
    int l = lb >> 2;

    const int t = threadIdx.x;
    const int w = t >> 5;
    const int lane = t & 31;

    wmma::fragment<wmma::accumulator, 16, 16, 16, float> acc[2];
    wmma::fill_fragment(acc[0], 0.0f);
    wmma::fill_fragment(acc[1], 0.0f);

    for (int c0 = 0; c0 < CC; c0 += 64) {
        for (int idx = t; idx < 512; idx += 256) {
            int row = idx >> 3, g = idx & 7;
            float4 v = *(const float4*)&lt[((size_t)lb * CC + c0 + row) * HWN + p0 + g * 4];
            __half2 h0 = __floats2half2_rn(v.x, v.y);
            __half2 h1 = __floats2half2_rn(v.z, v.w);
            *(uint2*)&aS[row * 40 + g * 4] = make_uint2(*(unsigned*)&h0, *(unsigned*)&h1);
        }
        for (int idx = t; idx < 1024; idx += 256) {
            int row = idx >> 3, g = idx & 7;
            *(uint4*)&bS[row * 72 + g * 8] =
                *(const uint4*)&d_cw_h[((size_t)(l * DD) + row) * CC + c0 + g * 8];
        }
        __syncthreads();

        #pragma unroll
        for (int kk = 0; kk < 4; kk++) {
            wmma::fragment<wmma::matrix_a, 16, 16, 16, __half, wmma::col_major> af[2];
            wmma::fragment<wmma::matrix_b, 16, 16, 16, __half, wmma::col_major> bf;
            #pragma unroll
            for (int i = 0; i < 2; i++)
                wmma::load_matrix_sync(af[i], &aS[(kk * 16) * 40 + i * 16], 40);
            wmma::load_matrix_sync(bf, &bS[(w * 16) * 72 + kk * 16], 72);
            #pragma unroll
            for (int i = 0; i < 2; i++)
                wmma::mma_sync(acc[i], af[i], bf, acc[i]);
        }
        __syncthreads();
    }

    #pragma unroll
    for (int i = 0; i < 2; i++) {
        wmma::store_matrix_sync(&scratch[w][0], acc[i], 16, wmma::mem_row_major);
        __syncwarp();
        int r = lane >> 1;
        int cbase = (lane & 1) * 8;
        __align__(16) __half2 hv[4];
        #pragma unroll
        for (int q = 0; q < 4; q++) {
            float a = scratch[w][r * 16 + cbase + 2 * q];
            float bq = scratch[w][r * 16 + cbase + 2 * q + 1];
            hv[q] = __floats2half2_rn(a, bq);
        }
        size_t px = (size_t)lb * HWN + p0 + i * 16 + r;
        *(uint4*)&d_feat_h[px * DD + w * 16 + cbase] = *(uint4*)hv;
        __syncwarp();
    }
}

// ---------------- final: binned GEMM, b = blockIdx.y, static smem --------------------
__global__ __launch_bounds__(256) void final_kernel(
    const float* __restrict__ ow, const float* __restrict__ ob,
    float* __restrict__ out, int N)
{
    __shared__ __align__(16) __half featG[64 * 136];   // [k][136] for this b
    __shared__ __align__(16) __half coefH[64 * 72];
    __shared__ __align__(16) __half coefL[64 * 72];
    __shared__ __align__(16) float scratch[8][256];
    __shared__ float partial[64 * 8];
    __shared__ int nidS[64];
    __shared__ float obS[64];

    int cid = blockIdx.x;
    if (cid >= d_numChunks) return;
    const int b = blockIdx.y;
    uint2 ch = d_chunks[cid];
    int bin = (int)(ch.x & 0xFFFF);
    int cnt = (int)(ch.x >> 16);
    int start = (int)ch.y;

    int x0 = (bin % 17) - 1;
    int y0 = (bin / 17) - 1;
    int cx0 = min(max(x0, 0), 15), cx1 = min(max(x0 + 1, 0), 15);
    int cy0 = min(max(y0, 0), 15), cy1 = min(max(y0 + 1, 0), 15);
    int pix[4] = {cy0 * 16 + cx0, cy0 * 16 + cx1, cy1 * 16 + cx0, cy1 * 16 + cx1};

    const int t = threadIdx.x;
    const int w = t >> 5;
    const int lane = t & 31;

    // ---- load patch for this b: featG[k][d], k = l*4+c | 48+l | zero ----
    for (int idx = t; idx < 64 * 16; idx += 256) {
        int k = idx >> 4, g = idx & 15;
        uint4 v;
        if (k < 48) {
            int l = k >> 2, c = k & 3;
            v = *(const uint4*)&d_feat_h[((size_t)(l * 4 + b) * HWN + pix[c]) * DD + g * 8];
        } else if (k < 60) {
            int l = k - 48;
            v = *(const uint4*)&d_gb_h[(l * 4 + b) * DD + g * 8];
        } else {
            v = make_uint4(0, 0, 0, 0);
        }
        *(uint4*)&featG[k * 136 + g * 8] = v;
    }

    // ---- build coefficient rows (threads 0..63, one point each) ----
    if (t < 64) {
        if (t < cnt) {
            int n = d_order[start + t];
            nidS[t] = n;
            obS[t] = ob[n];
            float s = d_sscale[n];
            float os = 1.0f - s;
            float pw[4];
            #pragma unroll
            for (int c = 0; c < 4; c++) pw[c] = d_pwv[n * 4 + c];
            #pragma unroll
            for (int l = 0; l < 12; l++) {
                float cl = d_wl[n * 12 + l];
                #pragma unroll
                for (int c = 0; c < 4; c++) {
                    float v = os * cl * pw[c];
                    __half h = __float2half_rn(v);
                    coefH[t * 72 + l * 4 + c] = h;
                    coefL[t * 72 + l * 4 + c] = __float2half_rn(v - __half2float(h));
                }
                float vg = s * cl;
                __half hg = __float2half_rn(vg);
                coefH[t * 72 + 48 + l] = hg;
                coefL[t * 72 + 48 + l] = __float2half_rn(vg - __half2float(hg));
            }
            #pragma unroll
            for (int k = 60; k < 64; k++) {
                coefH[t * 72 + k] = __float2half(0.0f);
                coefL[t * 72 + k] = __float2half(0.0f);
            }
        } else {
            for (int k = 0; k < 64; k++) {
                coefH[t * 72 + k] = __float2half(0.0f);
                coefL[t * 72 + k] = __float2half(0.0f);
            }
        }
    }
    __syncthreads();

    // ---- GEMM + epilogue; warp w owns d columns [w*16, w*16+16) ----
    wmma::fragment<wmma::accumulator, 16, 16, 16, float> acc[4];
    #pragma unroll
    for (int m = 0; m < 4; m++) wmma::fill_fragment(acc[m], 0.0f);

    #pragma unroll
    for (int kt = 0; kt < 4; kt++) {
        wmma::fragment<wmma::matrix_b, 16, 16, 16, __half, wmma::row_major> bf;
        wmma::load_matrix_sync(bf, &featG[(kt * 16) * 136 + w * 16], 136);
        #pragma unroll
        for (int m = 0; m < 4; m++) {
            wmma::fragment<wmma::matrix_a, 16, 16, 16, __half, wmma::row_major> af;
            wmma::load_matrix_sync(af, &coefH[(m * 16) * 72 + kt * 16], 72);
            wmma::mma_sync(acc[m], af, bf, acc[m]);
        }
        #pragma unroll
        for (int m = 0; m < 4; m++) {
            wmma::fragment<wmma::matrix_a, 16, 16, 16, __half, wmma::row_major> af;
            wmma::load_matrix_sync(af, &coefL[(m * 16) * 72 + kt * 16], 72);
            wmma::mma_sync(acc[m], af, bf, acc[m]);
        }
    }

    float* scw = &scratch[w][0];
    #pragma unroll
    for (int m = 0; m < 4; m++) {
        wmma::store_matrix_sync(scw, acc[m], 16, wmma::mem_row_major);
        __syncwarp();
        int r = lane >> 1;
        int p = m * 16 + r;
        float sum = 0.0f;
        if (p < cnt) {
            int dbase = w * 16 + (lane & 1) * 8;
            const float* owp = ow + (size_t)nidS[p] * DD + dbase;
            float4 o0 = *(const float4*)owp;
            float4 o1 = *(const float4*)(owp + 4);
            const float* vp = scw + r * 16 + (lane & 1) * 8;
            sum = vp[0] * o0.x + vp[1] * o0.y + vp[2] * o0.z + vp[3] * o0.w
                + vp[4] * o1.x + vp[5] * o1.y + vp[6] * o1.z + vp[7] * o1.w;
        }
        sum += __shfl_xor_sync(0xFFFFFFFFu, sum, 1);
        if ((lane & 1) == 0 && p < cnt) partial[p * 8 + w] = sum;
        __syncwarp();
    }
    __syncthreads();

    if (t < 64 && t < cnt) {
        float y = 0.0f;
        #pragma unroll
        for (int ww = 0; ww < 8; ww++) y += partial[t * 8 + ww];
        out[b * N + nidS[t]] = y * (1.0f / 128.0f) + obS[t];
    }
}

// ---------------- launch ----------------
extern "C" void kernel_launch(void* const* d_in, const int* in_sizes, int n_in,
                              void* d_out, int out_size) {
    const float* lt      = (const float*)d_in[0];
    const float* gt      = (const float*)d_in[1];
    const float* coords  = (const float*)d_in[2];
    const float* conv_w  = (const float*)d_in[3];
    const float* glob_w  = (const float*)d_in[4];
    const float* W1      = (const float*)d_in[5];
    const float* b1      = (const float*)d_in[6];
    const float* W2      = (const float*)d_in[7];
    const float* b2      = (const float*)d_in[8];
    const float* spaceW3 = (const float*)d_in[9];
    const float* layerW3 = (const float*)d_in[10];
    const float* scaleW3 = (const float*)d_in[11];
    const float* ow      = (const float*)d_in[12];
    const float* ob      = (const float*)d_in[13];
    int N = in_sizes[2] / 3;
    float* out = (float*)d_out;

    __half* cw_h; cudaGetSymbolAddress((void**)&cw_h, d_cw_h);

    static cudaStream_t s2 = nullptr, s3 = nullptr;
    static cudaEvent_t evFork = nullptr, evJ2 = nullptr, evJ3 = nullptr;
    if (s2 == nullptr) {
        cudaStreamCreateWithFlags(&s2, cudaStreamNonBlocking);
        cudaStreamCreateWithFlags(&s3, cudaStreamNonBlocking);
        cudaEventCreateWithFlags(&evFork, cudaEventDisableTiming);
        cudaEventCreateWithFlags(&evJ2, cudaEventDisableTiming);
        cudaEventCreateWithFlags(&evJ3, cudaEventDisableTiming);
        cudaFuncSetAttribute(selector_kernel,
                             cudaFuncAttributeMaxDynamicSharedMemorySize, SEL_SMEM_BYTES);
    }

    int nblk = (N + 31) / 32;

    prep_kernel<<<385, 256>>>(W1, W2);
    cudaEventRecord(evFork, 0);
    cudaStreamWaitEvent(s2, evFork, 0);
    cudaStreamWaitEvent(s3, evFork, 0);

    // s2: conv chain (independent until final)
    cvt_kernel<<<288, 256, 0, s2>>>(conv_w, cw_h, LL * DD * CC / 4);
    gb_kernel<<<dim3(48, 4), 128, 0, s2>>>(gt, glob_w);
    conv_kernel<<<384, 256, 0, s2>>>(lt);
    cudaEventRecord(evJ2, s2);

    // s3: heads 1,2 (2-term) -> reg scalar
    selector_kernel<<<dim3(nblk, 2), 256, SEL_SMEM_BYTES, s3>>>(
        coords, b1, b2, spaceW3, layerW3, scaleW3, N, 1);
    reg_kernel<<<1, 1, 0, s3>>>(out, N, out_size);
    cudaEventRecord(evJ3, s3);

    // main: head 0 (3-term) -> scan -> scatter
    selector_kernel<<<dim3(nblk, 1), 256, SEL_SMEM_BYTES>>>(
        coords, b1, b2, spaceW3, layerW3, scaleW3, N, 0);
    scan_kernel<<<1, 512>>>(out, N, out_size);
    scatter_kernel<<<(N + 255) / 256, 256>>>(N);

    cudaStreamWaitEvent(0, evJ2, 0);
    cudaStreamWaitEvent(0, evJ3, 0);
    final_kernel<<<dim3(NBINS + (N + CHSZ - 1) / CHSZ, 4), 256>>>(ow, ob, out, N);
}